// round 4
// baseline (speedup 1.0000x reference)
#include <cuda_runtime.h>
#include <math.h>

#define K_DIM 1000
#define N_DIM 1000
#define M_PTS 900000
#define SENTINEL -9999.0f

typedef unsigned long long u64;

// Scratch grid: packed cells. High 32 bits = (m+1) (scatter order priority,
// last-write-wins like XLA in-order scatter), low 32 bits = float bits of val.
__device__ u64 g_cells[K_DIM * N_DIM];

#define HALF_CELLS 500000

__global__ void init_cells_lo(void) {
    int i = blockIdx.x * blockDim.x + threadIdx.x;
    if (i < HALF_CELLS) g_cells[i] = 0ull;
}
__global__ void init_cells_hi(void) {
    int i = blockIdx.x * blockDim.x + threadIdx.x;
    if (i < HALF_CELLS) g_cells[HALF_CELLS + i] = 0ull;
}
__global__ void init_out(float* out) {
    int i = blockIdx.x * blockDim.x + threadIdx.x;
    if (i < K_DIM + N_DIM) out[i] = -INFINITY;
}

// Weight layout offsets (weight-index units; shared holds float2 dups)
#define OFF_W1 0
#define OFF_B1 126
#define OFF_W2 144
#define OFF_B2 792
#define OFF_W3 828
#define OFF_B3 2124
#define OFF_W4 2160
#define OFF_B4 2196
#define W_TOTAL 2197

__device__ __forceinline__ u64 fma2(u64 a, u64 b, u64 c) {
    u64 d;
    asm("fma.rn.f32x2 %0, %1, %2, %3;" : "=l"(d) : "l"(a), "l"(b), "l"(c));
    return d;
}

__device__ __forceinline__ u64 relu2(u64 a) {
    u64 r;
    asm("{\n\t"
        ".reg .f32 l, h;\n\t"
        "mov.b64 {l, h}, %1;\n\t"
        "max.f32 l, l, 0f00000000;\n\t"
        "max.f32 h, h, 0f00000000;\n\t"
        "mov.b64 %0, {l, h};\n\t"
        "}" : "=l"(r) : "l"(a));
    return r;
}

__device__ __forceinline__ u64 mk64(unsigned lo, unsigned hi) {
    return ((u64)hi << 32) | (u64)lo;
}

__global__ __launch_bounds__(128) void mlp_scatter_kernel(
    const float* __restrict__ xin, const int* __restrict__ tind,
    const float* __restrict__ w1, const float* __restrict__ b1,
    const float* __restrict__ w2, const float* __restrict__ b2,
    const float* __restrict__ w3, const float* __restrict__ b3,
    const float* __restrict__ w4, const float* __restrict__ b4)
{
    // Each weight duplicated into both f32x2 lanes: s[i] = (w_i, w_i).
    __shared__ float2 s[W_TOTAL + 1];

    int p = blockIdx.x * 128 + threadIdx.x;
    int m0 = 2 * p;
    bool active = (m0 < M_PTS);

    // Prefetch inputs + indices before the weight-staging barrier.
    u64 x[7];
    int2 rr = make_int2(0, 0), cc = make_int2(0, 0);
    if (active) {
        #pragma unroll
        for (int f = 0; f < 7; ++f)
            x[f] = *reinterpret_cast<const u64*>(&xin[f * M_PTS + m0]);
        rr = *reinterpret_cast<const int2*>(&tind[m0]);
        cc = *reinterpret_cast<const int2*>(&tind[M_PTS + m0]);
    }

    for (int i = threadIdx.x; i < W_TOTAL; i += 128) {
        float v;
        if (i < OFF_B1)       v = w1[i - OFF_W1];
        else if (i < OFF_W2)  v = b1[i - OFF_B1];
        else if (i < OFF_B2)  v = w2[i - OFF_W2];
        else if (i < OFF_W3)  v = b2[i - OFF_B2];
        else if (i < OFF_B3)  v = w3[i - OFF_W3];
        else if (i < OFF_W4)  v = b3[i - OFF_B3];
        else if (i < OFF_B4)  v = w4[i - OFF_W4];
        else                  v = b4[0];
        s[i] = make_float2(v, v);
    }
    if (threadIdx.x == 0) s[W_TOTAL] = make_float2(0.f, 0.f);
    __syncthreads();

    if (!active) return;

    const u64* sv = reinterpret_cast<const u64*>(s);

    // Layer 1: 7 -> 18
    u64 h1[18];
    #pragma unroll
    for (int o = 0; o < 18; ++o) {
        u64 a = sv[OFF_B1 + o];
        #pragma unroll
        for (int i = 0; i < 7; ++i)
            a = fma2(sv[OFF_W1 + o * 7 + i], x[i], a);
        h1[o] = relu2(a);
    }

    // Layer 2: 18 -> 36 (uint4 = 2 duplicated weights per LDS.128)
    u64 h2[36];
    #pragma unroll
    for (int o = 0; o < 36; ++o) {
        u64 a = sv[OFF_B2 + o];
        #pragma unroll
        for (int i = 0; i < 18; i += 2) {
            uint4 q = *reinterpret_cast<const uint4*>(&s[OFF_W2 + o * 18 + i]);
            a = fma2(mk64(q.x, q.y), h1[i], a);
            a = fma2(mk64(q.z, q.w), h1[i + 1], a);
        }
        h2[o] = relu2(a);
    }

    // Layer 3 + 4 fused: h3[o] is consumed immediately, never stored.
    u64 v = sv[OFF_B4];
    #pragma unroll
    for (int o = 0; o < 36; ++o) {
        u64 a = sv[OFF_B3 + o];
        #pragma unroll
        for (int i = 0; i < 36; i += 2) {
            uint4 q = *reinterpret_cast<const uint4*>(&s[OFF_W3 + o * 36 + i]);
            a = fma2(mk64(q.x, q.y), h2[i], a);
            a = fma2(mk64(q.z, q.w), h2[i + 1], a);
        }
        a = relu2(a);
        v = fma2(sv[OFF_W4 + o], a, v);
    }

    unsigned v0 = (unsigned)(v & 0xFFFFFFFFull);
    unsigned v1 = (unsigned)(v >> 32);

    u64 key0 = (((u64)(unsigned)(m0 + 1)) << 32) | (u64)v0;
    u64 key1 = (((u64)(unsigned)(m0 + 2)) << 32) | (u64)v1;
    atomicMax(&g_cells[rr.x * N_DIM + cc.x], key0);
    atomicMax(&g_cells[rr.y * N_DIM + cc.y], key1);
}

__device__ __forceinline__ float cell_val(u64 k) {
    return (k == 0ull) ? SENTINEL : __uint_as_float((unsigned)(k & 0xFFFFFFFFull));
}

// Order-preserving float atomic max (mixed signs; accumulator init -inf).
__device__ __forceinline__ void atomicMaxFloat(float* addr, float val) {
    if (val >= 0.0f) atomicMax((int*)addr, __float_as_int(val));
    else             atomicMin((unsigned int*)addr, __float_as_uint(val));
}

// Fused row+col max in ONE pass over the grid.
// grid (32, 4), block (32, 8). Block tile: 32 cols x 250 rows.
// Each warp handles one row per iteration (32 cols wide):
//   - warp shuffle-reduce -> row max contribution (lane 0 atomics out[row])
//   - per-lane register accumulates column max -> one atomic at the end.
__global__ void reduce_kernel(float* out) {
    int col = blockIdx.x * 32 + threadIdx.x;
    bool colok = (col < N_DIM);
    int r0 = blockIdx.y * 250;
    float cmax = -INFINITY;

    #pragma unroll 4
    for (int r = r0 + threadIdx.y; r < r0 + 250; r += 8) {
        float v = colok ? cell_val(g_cells[r * N_DIM + col]) : SENTINEL;
        cmax = fmaxf(cmax, v);
        float rv = v;
        #pragma unroll
        for (int d = 16; d; d >>= 1)
            rv = fmaxf(rv, __shfl_xor_sync(0xffffffffu, rv, d));
        if (threadIdx.x == 0) atomicMaxFloat(&out[r], rv);
    }
    if (colok) atomicMaxFloat(&out[K_DIM + col], fmaxf(cmax, SENTINEL));
}

extern "C" void kernel_launch(void* const* d_in, const int* in_sizes, int n_in,
                              void* d_out, int out_size) {
    const float* xin = (const float*)d_in[0];
    // d_in[1] = T_out (zeros, unused)
    const int*   tind = (const int*)d_in[2];
    const float* w1 = (const float*)d_in[3];
    const float* b1 = (const float*)d_in[4];
    const float* w2 = (const float*)d_in[5];
    const float* b2 = (const float*)d_in[6];
    const float* w3 = (const float*)d_in[7];
    const float* b3 = (const float*)d_in[8];
    const float* w4 = (const float*)d_in[9];
    const float* b4 = (const float*)d_in[10];
    float* out = (float*)d_out;

    // Three small init launches so the MLP is the 4th kernel launch —
    // that's the slot the ncu capture lands on.
    init_cells_lo<<<(HALF_CELLS + 255) / 256, 256>>>();
    init_cells_hi<<<(HALF_CELLS + 255) / 256, 256>>>();
    init_out<<<(K_DIM + N_DIM + 255) / 256, 256>>>(out);

    int pairs = M_PTS / 2;                 // 450000
    mlp_scatter_kernel<<<(pairs + 127) / 128, 128>>>(
        xin, tind, w1, b1, w2, b2, w3, b3, w4, b4);

    dim3 rb(32, 8), rg(32, 4);
    reduce_kernel<<<rg, rb>>>(out);
}

// round 5
// speedup vs baseline: 1.3086x; 1.3086x over previous
#include <cuda_runtime.h>
#include <math.h>

#define K_DIM 1000
#define N_DIM 1000
#define M_PTS 900000
#define SENTINEL -9999.0f

typedef unsigned long long u64;

// Scratch grid: packed cells. High 32 bits = (m+1) (scatter order priority,
// last-write-wins like XLA in-order scatter), low 32 bits = float bits of val.
__device__ u64 g_cells[K_DIM * N_DIM];

#define HALF_CELLS 500000

__global__ void init_cells_lo(void) {
    int i = blockIdx.x * blockDim.x + threadIdx.x;
    if (i < HALF_CELLS) g_cells[i] = 0ull;
}
__global__ void init_cells_hi(void) {
    int i = blockIdx.x * blockDim.x + threadIdx.x;
    if (i < HALF_CELLS) g_cells[HALF_CELLS + i] = 0ull;
}
__global__ void init_out(float* out) {
    int i = blockIdx.x * blockDim.x + threadIdx.x;
    if (i < N_DIM) out[K_DIM + i] = -INFINITY;  // col_max accumulators
}

// Weight layout offsets (weight-index units; shared holds float2 dups)
#define OFF_W1 0
#define OFF_B1 126
#define OFF_W2 144
#define OFF_B2 792
#define OFF_W3 828
#define OFF_B3 2124
#define OFF_W4 2160
#define OFF_B4 2196
#define W_TOTAL 2197

__device__ __forceinline__ u64 fma2(u64 a, u64 b, u64 c) {
    u64 d;
    asm("fma.rn.f32x2 %0, %1, %2, %3;" : "=l"(d) : "l"(a), "l"(b), "l"(c));
    return d;
}

__device__ __forceinline__ u64 relu2(u64 a) {
    u64 r;
    asm("{\n\t"
        ".reg .f32 l, h;\n\t"
        "mov.b64 {l, h}, %1;\n\t"
        "max.f32 l, l, 0f00000000;\n\t"
        "max.f32 h, h, 0f00000000;\n\t"
        "mov.b64 %0, {l, h};\n\t"
        "}" : "=l"(r) : "l"(a));
    return r;
}

__device__ __forceinline__ u64 mk64(unsigned lo, unsigned hi) {
    return ((u64)hi << 32) | (u64)lo;
}

// 4 points per thread (two f32x2 pairs a/b). Each weight LDS feeds both
// pairs -> shared-memory bytes per MAC halve vs 2-points/thread.
__global__ __launch_bounds__(128) void mlp_scatter_kernel(
    const float* __restrict__ xin, const int* __restrict__ tind,
    const float* __restrict__ w1, const float* __restrict__ b1,
    const float* __restrict__ w2, const float* __restrict__ b2,
    const float* __restrict__ w3, const float* __restrict__ b3,
    const float* __restrict__ w4, const float* __restrict__ b4)
{
    // Each weight duplicated into both f32x2 lanes: s[i] = (w_i, w_i).
    __shared__ float2 s[W_TOTAL + 1];

    int t = blockIdx.x * 128 + threadIdx.x;
    int m0 = 4 * t;
    bool active = (m0 < M_PTS);

    // Prefetch inputs + indices (one uint4 each; m0 % 4 == 0 -> 16B aligned).
    u64 xa[7], xb[7];
    int4 ri = make_int4(0, 0, 0, 0), ci = make_int4(0, 0, 0, 0);
    if (active) {
        #pragma unroll
        for (int f = 0; f < 7; ++f) {
            uint4 q = *reinterpret_cast<const uint4*>(&xin[f * M_PTS + m0]);
            xa[f] = mk64(q.x, q.y);
            xb[f] = mk64(q.z, q.w);
        }
        ri = *reinterpret_cast<const int4*>(&tind[m0]);
        ci = *reinterpret_cast<const int4*>(&tind[M_PTS + m0]);
    }

    for (int i = threadIdx.x; i < W_TOTAL; i += 128) {
        float v;
        if (i < OFF_B1)       v = w1[i - OFF_W1];
        else if (i < OFF_W2)  v = b1[i - OFF_B1];
        else if (i < OFF_B2)  v = w2[i - OFF_W2];
        else if (i < OFF_W3)  v = b2[i - OFF_B2];
        else if (i < OFF_B3)  v = w3[i - OFF_W3];
        else if (i < OFF_W4)  v = b3[i - OFF_B3];
        else if (i < OFF_B4)  v = w4[i - OFF_W4];
        else                  v = b4[0];
        s[i] = make_float2(v, v);
    }
    if (threadIdx.x == 0) s[W_TOTAL] = make_float2(0.f, 0.f);
    __syncthreads();

    if (!active) return;

    const u64* sv = reinterpret_cast<const u64*>(s);

    // Layer 1: 7 -> 18
    u64 h1a[18], h1b[18];
    #pragma unroll
    for (int o = 0; o < 18; ++o) {
        u64 bb = sv[OFF_B1 + o];
        u64 aa = bb, ab = bb;
        #pragma unroll
        for (int i = 0; i < 7; ++i) {
            u64 w = sv[OFF_W1 + o * 7 + i];
            aa = fma2(w, xa[i], aa);
            ab = fma2(w, xb[i], ab);
        }
        h1a[o] = relu2(aa);
        h1b[o] = relu2(ab);
    }

    // Layer 2: 18 -> 36 (uint4 = 2 duplicated weights per LDS.128)
    u64 h2a[36], h2b[36];
    #pragma unroll
    for (int o = 0; o < 36; ++o) {
        u64 bb = sv[OFF_B2 + o];
        u64 aa = bb, ab = bb;
        #pragma unroll
        for (int i = 0; i < 18; i += 2) {
            uint4 q = *reinterpret_cast<const uint4*>(&s[OFF_W2 + o * 18 + i]);
            u64 w0 = mk64(q.x, q.y), w1v = mk64(q.z, q.w);
            aa = fma2(w0, h1a[i], aa);
            ab = fma2(w0, h1b[i], ab);
            aa = fma2(w1v, h1a[i + 1], aa);
            ab = fma2(w1v, h1b[i + 1], ab);
        }
        h2a[o] = relu2(aa);
        h2b[o] = relu2(ab);
    }

    // Layer 3 + 4 fused: h3[o] consumed immediately, never stored.
    u64 va = sv[OFF_B4], vb = va;
    #pragma unroll
    for (int o = 0; o < 36; ++o) {
        u64 bb = sv[OFF_B3 + o];
        u64 aa = bb, ab = bb;
        #pragma unroll
        for (int i = 0; i < 36; i += 2) {
            uint4 q = *reinterpret_cast<const uint4*>(&s[OFF_W3 + o * 36 + i]);
            u64 w0 = mk64(q.x, q.y), w1v = mk64(q.z, q.w);
            aa = fma2(w0, h2a[i], aa);
            ab = fma2(w0, h2b[i], ab);
            aa = fma2(w1v, h2a[i + 1], aa);
            ab = fma2(w1v, h2b[i + 1], ab);
        }
        u64 w4o = sv[OFF_W4 + o];
        va = fma2(w4o, relu2(aa), va);
        vb = fma2(w4o, relu2(ab), vb);
    }

    unsigned v0 = (unsigned)(va & 0xFFFFFFFFull);
    unsigned v1 = (unsigned)(va >> 32);
    unsigned v2 = (unsigned)(vb & 0xFFFFFFFFull);
    unsigned v3 = (unsigned)(vb >> 32);

    atomicMax(&g_cells[ri.x * N_DIM + ci.x],
              (((u64)(unsigned)(m0 + 1)) << 32) | (u64)v0);
    atomicMax(&g_cells[ri.y * N_DIM + ci.y],
              (((u64)(unsigned)(m0 + 2)) << 32) | (u64)v1);
    atomicMax(&g_cells[ri.z * N_DIM + ci.z],
              (((u64)(unsigned)(m0 + 3)) << 32) | (u64)v2);
    atomicMax(&g_cells[ri.w * N_DIM + ci.w],
              (((u64)(unsigned)(m0 + 4)) << 32) | (u64)v3);
}

__device__ __forceinline__ float cell_val(u64 k) {
    return (k == 0ull) ? SENTINEL : __uint_as_float((unsigned)(k & 0xFFFFFFFFull));
}

__global__ void row_max_kernel(float* out) {
    int i = blockIdx.x;
    __shared__ float red[256];
    float mx = SENTINEL;
    #pragma unroll
    for (int j = threadIdx.x; j < N_DIM; j += 256)
        mx = fmaxf(mx, cell_val(g_cells[i * N_DIM + j]));
    red[threadIdx.x] = mx;
    __syncthreads();
    #pragma unroll
    for (int s2 = 128; s2 > 0; s2 >>= 1) {
        if (threadIdx.x < s2)
            red[threadIdx.x] = fmaxf(red[threadIdx.x], red[threadIdx.x + s2]);
        __syncthreads();
    }
    if (threadIdx.x == 0) out[i] = red[0];
}

// Order-preserving float atomic max (mixed signs; accumulator init -inf).
__device__ __forceinline__ void atomicMaxFloat(float* addr, float val) {
    if (val >= 0.0f) atomicMax((int*)addr, __float_as_int(val));
    else             atomicMin((unsigned int*)addr, __float_as_uint(val));
}

// blockDim (64,4): 64 cols wide, 64-row strip per blockIdx.y -> 256 blocks.
__global__ void col_max_kernel(float* out) {
    int j = blockIdx.x * 64 + threadIdx.x;
    float mx = SENTINEL;
    if (j < N_DIM) {
        int r0 = blockIdx.y * 64;
        int r1 = min(r0 + 64, K_DIM);
        for (int r = r0 + threadIdx.y; r < r1; r += 4)
            mx = fmaxf(mx, cell_val(g_cells[r * N_DIM + j]));
    }
    __shared__ float red[4][64];
    red[threadIdx.y][threadIdx.x] = mx;
    __syncthreads();
    if (threadIdx.y == 0 && j < N_DIM) {
        float m2 = fmaxf(fmaxf(red[0][threadIdx.x], red[1][threadIdx.x]),
                         fmaxf(red[2][threadIdx.x], red[3][threadIdx.x]));
        atomicMaxFloat(&out[K_DIM + j], m2);
    }
}

extern "C" void kernel_launch(void* const* d_in, const int* in_sizes, int n_in,
                              void* d_out, int out_size) {
    const float* xin = (const float*)d_in[0];
    // d_in[1] = T_out (zeros, unused)
    const int*   tind = (const int*)d_in[2];
    const float* w1 = (const float*)d_in[3];
    const float* b1 = (const float*)d_in[4];
    const float* w2 = (const float*)d_in[5];
    const float* b2 = (const float*)d_in[6];
    const float* w3 = (const float*)d_in[7];
    const float* b3 = (const float*)d_in[8];
    const float* w4 = (const float*)d_in[9];
    const float* b4 = (const float*)d_in[10];
    float* out = (float*)d_out;

    // Three small init launches keep the MLP as the 4th kernel launch —
    // the slot the ncu capture lands on.
    init_cells_lo<<<(HALF_CELLS + 255) / 256, 256>>>();
    init_cells_hi<<<(HALF_CELLS + 255) / 256, 256>>>();
    init_out<<<(N_DIM + 255) / 256, 256>>>(out);

    int quads = M_PTS / 4;                 // 225000
    mlp_scatter_kernel<<<(quads + 127) / 128, 128>>>(
        xin, tind, w1, b1, w2, b2, w3, b3, w4, b4);

    row_max_kernel<<<K_DIM, 256>>>(out);
    dim3 cb(64, 4), cg(16, 16);
    col_max_kernel<<<cg, cb>>>(out);
}